// round 17
// baseline (speedup 1.0000x reference)
#include <cuda_runtime.h>
#include <cuda_fp16.h>

#define N_NODES 50000
#define N_EDGES 800000
#define F1 128
#define F2 16

#define TILE 512
#define NB   ((N_NODES + TILE - 1) / TILE)   // 98

// Scratch (allocation-free contract: __device__ globals)
__device__ int       g_cnt [N_NODES];        // zero at load; self-re-zeroed
__device__ int       g_off [N_NODES + 1];    // exclusive offsets (NOT mutated)
__device__ long long g_state[NB];            // scan lookback
__device__ int4      g_pos4[N_EDGES / 4];    // per-edge slot within its dst node
__device__ int       g_src [N_EDGES];
__device__ float     g_dinv[N_NODES];
__device__ __align__(16) __half2 g_xh [N_NODES * (F1 / 2)];  // x in fp16
__device__ __align__(16) __half2 g_wh [64 * F1];             // W k-pair packed fp16
__device__ __align__(16) __half2 g_h1h[N_NODES * (F1 / 2)];  // h1 * dinv[row], fp16
__device__ float4    g_h2  [N_NODES * (F2 / 4)];             // h2 * dinv[row], fp32

// ---------------------------------------------------------------------------
// 1) in-degree counts (slot = atomicAdd return) + fp16 pre-conversion of x, W.
//    W packed as k-pairs: g_wh[kp*128 + n] = {W[2kp][n], W[2kp+1][n]}.
// ---------------------------------------------------------------------------
__global__ void k_count(const int* __restrict__ ei,
                        const float* __restrict__ x,
                        const float* __restrict__ W) {
    int t = blockIdx.x * blockDim.x + threadIdx.x;

    if (t < N_EDGES / 4) {
        int4 c = ((const int4*)(ei + N_EDGES))[t];
        int4 p = make_int4(0, 0, 0, 0);
        if ((unsigned)c.x < N_NODES) p.x = atomicAdd(&g_cnt[c.x], 1);
        if ((unsigned)c.y < N_NODES) p.y = atomicAdd(&g_cnt[c.y], 1);
        if ((unsigned)c.z < N_NODES) p.z = atomicAdd(&g_cnt[c.z], 1);
        if ((unsigned)c.w < N_NODES) p.w = atomicAdd(&g_cnt[c.w], 1);
        g_pos4[t] = p;
    }

    // x -> fp16 (1.6M float4, grid-stride)
    const float4* x4 = (const float4*)x;
    int nthr = gridDim.x * blockDim.x;
    for (int i = t; i < N_NODES * 32; i += nthr) {
        float4 v = x4[i];
        __half2 h0 = __floats2half2_rn(v.x, v.y);
        __half2 h1 = __floats2half2_rn(v.z, v.w);
        *(uint2*)&g_xh[(size_t)i * 2] =
            make_uint2(*(unsigned*)&h0, *(unsigned*)&h1);
    }

    // W -> k-pair packed fp16 (64 kp x 32 n4 = 2048 uint4 elements)
    if (t < 64 * 32) {
        int kp = t >> 5;
        int n4 = t & 31;
        const float4* W4 = (const float4*)W;
        float4 va = W4[(size_t)(2 * kp) * 32 + n4];
        float4 vb = W4[(size_t)(2 * kp + 1) * 32 + n4];
        __half2* d = &g_wh[kp * 128 + n4 * 4];
        d[0] = __floats2half2_rn(va.x, vb.x);
        d[1] = __floats2half2_rn(va.y, vb.y);
        d[2] = __floats2half2_rn(va.z, vb.z);
        d[3] = __floats2half2_rn(va.w, vb.w);
    }
}

// ---------------------------------------------------------------------------
// 2) single-kernel scan with decoupled lookback (98 blocks, all wave-1).
// ---------------------------------------------------------------------------
__global__ __launch_bounds__(TILE) void k_scan() {
    __shared__ int sh[TILE];
    __shared__ int s_ex;
    int t = threadIdx.x, bid = blockIdx.x;
    int i = bid * TILE + t;

    int c = (i < N_NODES) ? g_cnt[i] : 0;
    if (i < N_NODES) { g_dinv[i] = rsqrtf((float)(c + 1)); g_cnt[i] = 0; }

    sh[t] = c;
    __syncthreads();
    #pragma unroll
    for (int off = 1; off < TILE; off <<= 1) {
        int u = (t >= off) ? sh[t - off] : 0;
        __syncthreads();
        sh[t] += u;
        __syncthreads();
    }
    int total = sh[TILE - 1];

    if (t == 0) {
        long long st = (bid == 0)
            ? ((2LL << 32) | (unsigned)total)
            : ((1LL << 32) | (unsigned)total);
        atomicExch((unsigned long long*)&g_state[bid], (unsigned long long)st);
        if (bid == 0) s_ex = 0;
    }

    if (bid > 0 && t < 32) {
        int ex = 0, base = bid - 1;
        while (true) {
            int j = base - t;
            long long st;
            if (j >= 0) st = *(volatile long long*)&g_state[j];
            else        st = (2LL << 32);
            int flag = (int)(st >> 32);
            int val  = (int)(st & 0xffffffffLL);
            unsigned rdy = __ballot_sync(0xffffffffu, flag != 0);
            if (rdy != 0xffffffffu) continue;
            unsigned pref = __ballot_sync(0xffffffffu, flag == 2);
            int firstP = (pref == 0) ? 32 : (__ffs(pref) - 1);
            int contrib = (t <= firstP) ? val : 0;
            #pragma unroll
            for (int o = 16; o >= 1; o >>= 1)
                contrib += __shfl_xor_sync(0xffffffffu, contrib, o);
            ex += contrib;
            if (firstP < 32) break;
            base -= 32;
        }
        if (t == 0) {
            s_ex = ex;
            atomicExch((unsigned long long*)&g_state[bid],
                       (unsigned long long)((2LL << 32) | (unsigned)(ex + total)));
        }
    }
    __syncthreads();
    if (i < N_NODES) g_off[i] = s_ex + sh[t] - c;
    if (i == N_NODES - 1) g_off[N_NODES] = s_ex + sh[t];
}

// ---------------------------------------------------------------------------
// 3) fill source lists — NO atomics: slot = off[c] + pos[e].
// ---------------------------------------------------------------------------
__global__ void k_fill(const int* __restrict__ ei) {
    int t = blockIdx.x * blockDim.x + threadIdx.x;
    if (t < NB) g_state[t] = 0;
    if (t < N_EDGES / 4) {
        int4 r = ((const int4*)ei)[t];
        int4 c = ((const int4*)(ei + N_EDGES))[t];
        int4 p = g_pos4[t];
        if ((unsigned)r.x < N_NODES && (unsigned)c.x < N_NODES)
            g_src[g_off[c.x] + p.x] = r.x;
        if ((unsigned)r.y < N_NODES && (unsigned)c.y < N_NODES)
            g_src[g_off[c.y] + p.y] = r.y;
        if ((unsigned)r.z < N_NODES && (unsigned)c.z < N_NODES)
            g_src[g_off[c.z] + p.z] = r.z;
        if ((unsigned)r.w < N_NODES && (unsigned)c.w < N_NODES)
            g_src[g_off[c.w] + p.w] = r.w;
    }
}

// ---------------------------------------------------------------------------
// 4) h1s = (x @ W1) * dinv[row], fp16 mma m16n8k16.
//    Inputs already fp16 -> staging is pure uint4 copies (no cvt, no fp32 W).
//    256 thr / 8 warps, 64x128 tile, warps 4(M)x2(N).
// ---------------------------------------------------------------------------
__global__ __launch_bounds__(256) void k_gemm1() {
    __shared__ __half2 xs[64 * 36];    // [row][kp]  (kp = k/2 within chunk)
    __shared__ __half2 ws[32 * 136];   // [kp][n]    element = {W[2k][n], W[2k+1][n]}

    const int tid  = threadIdx.x;
    const int warp = tid >> 5;       // 0..7
    const int wm   = warp & 3;       // M tile 0..3
    const int wn   = warp >> 2;      // N half 0..1
    const int lane = tid & 31;
    const int g    = lane >> 2;      // 0..7
    const int tig  = lane & 3;       // 0..3
    const int row0 = blockIdx.x * 64;

    float c[8][4];
    #pragma unroll
    for (int nt = 0; nt < 8; nt++)
        #pragma unroll
        for (int q = 0; q < 4; q++) c[nt][q] = 0.f;

    const uint4* xv = (const uint4*)g_xh;   // per row: 16 uint4
    const uint4* wv = (const uint4*)g_wh;   // per kp row: 32 uint4

    for (int kc = 0; kc < 2; kc++) {             // K chunks of 64
        // stage x: 64 rows x 8 uint4 = 512
        #pragma unroll
        for (int it = 0; it < 2; it++) {
            int idx = it * 256 + tid;
            int r   = idx >> 3;
            int u4  = idx & 7;
            uint4 v = make_uint4(0u, 0u, 0u, 0u);
            if (row0 + r < N_NODES)
                v = xv[(size_t)(row0 + r) * 16 + kc * 8 + u4];
            *(uint4*)&xs[r * 36 + u4 * 4] = v;
        }
        // stage W: 32 kp x 32 uint4 = 1024 (already packed)
        #pragma unroll
        for (int it = 0; it < 4; it++) {
            int idx = it * 256 + tid;
            int kp  = idx >> 5;
            int n4  = idx & 31;
            *(uint4*)&ws[kp * 136 + n4 * 4] = wv[(size_t)(kc * 32 + kp) * 32 + n4];
        }
        __syncthreads();

        #pragma unroll
        for (int ks = 0; ks < 4; ks++) {         // 4 x k16 per chunk
            int ar = (wm * 16 + g) * 36 + ks * 8 + tig;
            unsigned a0 = *(const unsigned*)&xs[ar];
            unsigned a1 = *(const unsigned*)&xs[ar + 8 * 36];
            unsigned a2 = *(const unsigned*)&xs[ar + 4];
            unsigned a3 = *(const unsigned*)&xs[ar + 8 * 36 + 4];

            int b0r = (ks * 8 + tig) * 136 + wn * 64 + g;
            int b1r = (ks * 8 + tig + 4) * 136 + wn * 64 + g;
            #pragma unroll
            for (int nt = 0; nt < 8; nt++) {
                unsigned b0 = *(const unsigned*)&ws[b0r + nt * 8];
                unsigned b1 = *(const unsigned*)&ws[b1r + nt * 8];
                asm("mma.sync.aligned.m16n8k16.row.col.f32.f16.f16.f32 "
                    "{%0,%1,%2,%3}, {%4,%5,%6,%7}, {%8,%9}, {%0,%1,%2,%3};"
                    : "+f"(c[nt][0]), "+f"(c[nt][1]), "+f"(c[nt][2]), "+f"(c[nt][3])
                    : "r"(a0), "r"(a1), "r"(a2), "r"(a3), "r"(b0), "r"(b1));
            }
        }
        __syncthreads();
    }

    // store fp16, pre-scaled by dinv[row]
    int ma = row0 + wm * 16 + g;
    int mb = ma + 8;
    float da = (ma < N_NODES) ? g_dinv[ma] : 0.f;
    float db = (mb < N_NODES) ? g_dinv[mb] : 0.f;
    #pragma unroll
    for (int nt = 0; nt < 8; nt++) {
        int c2 = wn * 32 + nt * 4 + tig;         // half2 column (of 64)
        if (ma < N_NODES)
            g_h1h[(size_t)ma * 64 + c2] = __floats2half2_rn(c[nt][0] * da, c[nt][1] * da);
        if (mb < N_NODES)
            g_h1h[(size_t)mb * 64 + c2] = __floats2half2_rn(c[nt][2] * db, c[nt][3] * db);
    }
}

// ---------------------------------------------------------------------------
// 5) fused layer-1: gather pre-scaled h1s + bias + ReLU + @W2.
// ---------------------------------------------------------------------------
__global__ __launch_bounds__(256) void k_layer1(const float* __restrict__ b1,
                                                const float* __restrict__ W2) {
    int row  = (blockIdx.x * 256 + threadIdx.x) >> 5;
    int lane = threadIdx.x & 31;
    if (row >= N_NODES) return;

    float dc = g_dinv[row];

    const uint2* h1v = (const uint2*)g_h1h;     // 4 halfs per element

    uint2  su = h1v[(size_t)row * 32 + lane];
    float2 s0 = __half22float2(*(__half2*)&su.x);
    float2 s1 = __half22float2(*(__half2*)&su.y);
    float4 acc = make_float4(s0.x, s0.y, s1.x, s1.y);   // self term

    int e0 = g_off[row];
    int e1 = g_off[row + 1];
    int r_nxt = (e0 < e1) ? g_src[e0] : 0;
    for (int e = e0; e < e1; e++) {
        int r = r_nxt;
        r_nxt = g_src[(e + 1 < e1) ? e + 1 : e];        // branchless prefetch
        uint2  u  = h1v[(size_t)r * 32 + lane];
        float2 v0 = __half22float2(*(__half2*)&u.x);
        float2 v1 = __half22float2(*(__half2*)&u.y);
        acc.x += v0.x; acc.y += v0.y; acc.z += v1.x; acc.w += v1.y;
    }

    float4 b = ((const float4*)b1)[lane];
    float v[4];
    v[0] = fmaxf(fmaf(acc.x, dc, b.x), 0.f);
    v[1] = fmaxf(fmaf(acc.y, dc, b.y), 0.f);
    v[2] = fmaxf(fmaf(acc.z, dc, b.z), 0.f);
    v[3] = fmaxf(fmaf(acc.w, dc, b.w), 0.f);

    float p[16];
    #pragma unroll
    for (int j = 0; j < 16; j++) p[j] = 0.f;

    #pragma unroll
    for (int q = 0; q < 4; q++) {
        int k = lane * 4 + q;
        #pragma unroll
        for (int j4 = 0; j4 < 4; j4++) {
            float4 ww = ((const float4*)W2)[k * 4 + j4];
            p[j4 * 4 + 0] = fmaf(v[q], ww.x, p[j4 * 4 + 0]);
            p[j4 * 4 + 1] = fmaf(v[q], ww.y, p[j4 * 4 + 1]);
            p[j4 * 4 + 2] = fmaf(v[q], ww.z, p[j4 * 4 + 2]);
            p[j4 * 4 + 3] = fmaf(v[q], ww.w, p[j4 * 4 + 3]);
        }
    }

    #pragma unroll
    for (int off = 16; off >= 1; off >>= 1)
        #pragma unroll
        for (int j = 0; j < 16; j++)
            p[j] += __shfl_xor_sync(0xffffffffu, p[j], off);

    if (lane < 16) ((float*)g_h2)[row * F2 + lane] = p[lane] * dc;   // pre-scaled
}

// ---------------------------------------------------------------------------
// 6) fused layer-2: gather pre-scaled h2s + bias + log_softmax.
// ---------------------------------------------------------------------------
__global__ __launch_bounds__(256) void k_layer2(const float* __restrict__ b2,
                                                float* __restrict__ out) {
    int row  = (blockIdx.x * 256 + threadIdx.x) >> 5;
    int lane = threadIdx.x & 31;
    if (row >= N_NODES) return;

    int j = lane & 15;
    float dc = g_dinv[row];

    const float* h2 = (const float*)g_h2;
    float acc = h2[row * F2 + j];                       // self term

    int e0 = g_off[row];
    int e1 = g_off[row + 1];
    int r_nxt = (e0 < e1) ? g_src[e0] : 0;
    for (int e = e0; e < e1; e++) {
        int r = r_nxt;
        r_nxt = g_src[(e + 1 < e1) ? e + 1 : e];
        acc += h2[r * F2 + j];
    }
    acc = fmaf(acc, dc, b2[j]);

    float m = acc;
    #pragma unroll
    for (int off = 8; off >= 1; off >>= 1)
        m = fmaxf(m, __shfl_xor_sync(0xffffffffu, m, off));

    float s = __expf(acc - m);
    #pragma unroll
    for (int off = 8; off >= 1; off >>= 1)
        s += __shfl_xor_sync(0xffffffffu, s, off);

    if (lane < 16) out[row * F2 + lane] = (acc - m) - logf(s);
}

// ---------------------------------------------------------------------------
extern "C" void kernel_launch(void* const* d_in, const int* in_sizes, int n_in,
                              void* d_out, int out_size) {
    const float* x  = (const float*)d_in[0];
    const int*   ei = (const int*)d_in[1];     // int32 (JAX x64 disabled)
    const float* W1 = (const float*)d_in[2];
    const float* b1 = (const float*)d_in[3];
    const float* W2 = (const float*)d_in[4];
    const float* b2 = (const float*)d_in[5];
    float* out = (float*)d_out;

    (void)in_sizes; (void)n_in; (void)out_size;

    k_count <<<(N_EDGES / 4 + 255) / 256, 256>>>(ei, x, W1);
    k_scan  <<<NB, TILE>>>();
    k_fill  <<<(N_EDGES / 4 + 255) / 256, 256>>>(ei);
    k_gemm1 <<<(N_NODES + 63) / 64, 256>>>();
    k_layer1<<<(N_NODES * 32 + 255) / 256, 256>>>(b1, W2);
    k_layer2<<<(N_NODES * 32 + 255) / 256, 256>>>(b2, out);
}